// round 9
// baseline (speedup 1.0000x reference)
#include <cuda_runtime.h>
#include <cuda_fp16.h>

// Problem geometry (fixed per reference setup_inputs)
#define B_ 2
#define D_ 160
#define H_ 192
#define W_ 160
constexpr size_t N_  = (size_t)B_ * D_ * H_ * W_;   // 9,830,400
constexpr size_t HW_ = (size_t)H_ * W_;
#define WG_ 40   // float4 groups along w
#define NHC_ 12  // h-chunks (16 rows each)
#define NDC_ 16  // d-chunks (10 slices each)
#define DS_  ((int)(HW_ / 4))   // uint2 elements per d-slice (7680)

typedef unsigned long long u64;

// Intermediate: 5 channels (I_s, J_s, I2_s, J2_s, IJ_s), W+H convolved, fp16.
__device__ __half g_A[5 * N_];
__device__ double g_acc;
__device__ unsigned g_tk;

// ---------------------------------------------------------------------------
// Helpers
// ---------------------------------------------------------------------------
__device__ __forceinline__ float4 f4z() { return make_float4(0.f, 0.f, 0.f, 0.f); }
__device__ __forceinline__ __half2 u2h(unsigned u) { return *(__half2*)&u; }

// Packed f32x2 (Blackwell): two fp32 lanes per instruction.
__device__ __forceinline__ u64 pk2(float x, float y) {
    u64 r; asm("mov.b64 %0, {%1,%2};" : "=l"(r) : "f"(x), "f"(y)); return r;
}
__device__ __forceinline__ float2 upk2(u64 u) {
    float2 r; asm("mov.b64 {%0,%1}, %2;" : "=f"(r.x), "=f"(r.y) : "l"(u)); return r;
}
__device__ __forceinline__ u64 add2(u64 a, u64 b) {
    u64 r; asm("add.rn.f32x2 %0, %1, %2;" : "=l"(r) : "l"(a), "l"(b)); return r;
}
__device__ __forceinline__ u64 mul2(u64 a, u64 b) {
    u64 r; asm("mul.rn.f32x2 %0, %1, %2;" : "=l"(r) : "l"(a), "l"(b)); return r;
}
// a - b  ==  a + (b with both sign bits flipped)  (avoids sub.rn.f32x2)
__device__ __forceinline__ u64 sub2(u64 a, u64 b) {
    return add2(a, b ^ 0x8000000080000000ULL);
}

// 9-tap window sums for 4 lanes from 12 taps (x[0] = w-4). Packed head.
__device__ __forceinline__ void win9p(const float* x, float* w) {
    u64 s8 = add2(add2(pk2(x[0], x[1]), pk2(x[2], x[3])),
                  add2(pk2(x[4], x[5]), pk2(x[6], x[7])));
    float2 t = upk2(s8);
    float s = t.x + t.y + x[8];
    w[0] = s;
    s += x[9]  - x[0]; w[1] = s;
    s += x[10] - x[1]; w[2] = s;
    s += x[11] - x[2]; w[3] = s;
}

// Convert two packed-f32x2 accumulators (4 lanes) to 4 fp16 for store.
__device__ __forceinline__ uint2 h4(u64 lo, u64 hi) {
    float2 a = upk2(lo), b = upk2(hi);
    __half2 l = __floats2half2_rn(a.x, a.y);
    __half2 h = __floats2half2_rn(b.x, b.y);
    uint2 r; r.x = *(unsigned*)&l; r.y = *(unsigned*)&h; return r;
}

// ---------------------------------------------------------------------------
// Fused pass 1+2: 9-tap box sums along W and H. f32x2-packed window math,
// fp32 h-slide accumulators (packed), fp16 output.
// Thread = (plane, h-chunk of 16, 4-wide w group). 153,600 threads.
// ---------------------------------------------------------------------------
__global__ void __launch_bounds__(256) k_p12(const float* __restrict__ I,
                                             const float* __restrict__ J) {
    const int t     = blockIdx.x * blockDim.x + threadIdx.x;
    const int g     = t % WG_;
    const int ch    = (t / WG_) % NHC_;
    const int plane = t / (WG_ * NHC_);
    const int h0    = ch * 16;

    if (t == 0) { g_acc = 0.0; g_tk = 0u; }

    const size_t pbase = (size_t)plane * HW_;
    const float4* __restrict__ I4 = (const float4*)(I + pbase);
    const float4* __restrict__ J4 = (const float4*)(J + pbase);

    u64 S[5][2];
#pragma unroll
    for (int c = 0; c < 5; c++) { S[c][0] = 0ull; S[c][1] = 0ull; }

    auto fold = [&](int c, const float* w, bool add) {
        u64 w01 = pk2(w[0], w[1]), w23 = pk2(w[2], w[3]);
        if (add) { S[c][0] = add2(S[c][0], w01); S[c][1] = add2(S[c][1], w23); }
        else     { S[c][0] = sub2(S[c][0], w01); S[c][1] = sub2(S[c][1], w23); }
    };

    auto accum = [&](const float4* rI, const float4* rJ, bool add) {
        float4 qa0 = (g > 0)       ? __ldg(rI + g - 1) : f4z();
        float4 qa1 =                 __ldg(rI + g);
        float4 qa2 = (g < WG_ - 1) ? __ldg(rI + g + 1) : f4z();
        float4 qb0 = (g > 0)       ? __ldg(rJ + g - 1) : f4z();
        float4 qb1 =                 __ldg(rJ + g);
        float4 qb2 = (g < WG_ - 1) ? __ldg(rJ + g + 1) : f4z();

        float a[12] = {qa0.x,qa0.y,qa0.z,qa0.w, qa1.x,qa1.y,qa1.z,qa1.w, qa2.x,qa2.y,qa2.z,qa2.w};
        float b[12] = {qb0.x,qb0.y,qb0.z,qb0.w, qb1.x,qb1.y,qb1.z,qb1.w, qb2.x,qb2.y,qb2.z,qb2.w};

        float w[4], p[12];
        win9p(a, w); fold(0, w, add);
        win9p(b, w); fold(1, w, add);

        // packed products (aligned pairs), then window
#pragma unroll
        for (int j = 0; j < 6; j++) {
            float2 r = upk2(mul2(pk2(a[2*j], a[2*j+1]), pk2(a[2*j], a[2*j+1])));
            p[2*j] = r.x; p[2*j+1] = r.y;
        }
        win9p(p, w); fold(2, w, add);
#pragma unroll
        for (int j = 0; j < 6; j++) {
            float2 r = upk2(mul2(pk2(b[2*j], b[2*j+1]), pk2(b[2*j], b[2*j+1])));
            p[2*j] = r.x; p[2*j+1] = r.y;
        }
        win9p(p, w); fold(3, w, add);
#pragma unroll
        for (int j = 0; j < 6; j++) {
            float2 r = upk2(mul2(pk2(a[2*j], a[2*j+1]), pk2(b[2*j], b[2*j+1])));
            p[2*j] = r.x; p[2*j+1] = r.y;
        }
        win9p(p, w); fold(4, w, add);
    };

    auto store = [&](int ho) {
        const size_t o = pbase + (size_t)ho * W_ + (size_t)g * 4;
        *(uint2*)&g_A[0*N_ + o] = h4(S[0][0], S[0][1]);
        *(uint2*)&g_A[1*N_ + o] = h4(S[1][0], S[1][1]);
        *(uint2*)&g_A[2*N_ + o] = h4(S[2][0], S[2][1]);
        *(uint2*)&g_A[3*N_ + o] = h4(S[3][0], S[3][1]);
        *(uint2*)&g_A[4*N_ + o] = h4(S[4][0], S[4][1]);
    };

    if (ch > 0 && ch < NHC_ - 1) {
        // Interior: rows h0-4 .. h0+20 all inside [0, H) -> no bounds checks.
        const float4* aI = I4 + (size_t)(h0 - 4) * WG_;
        const float4* aJ = J4 + (size_t)(h0 - 4) * WG_;
#pragma unroll 3
        for (int k = 0; k < 9; k++) { accum(aI, aJ, true); aI += WG_; aJ += WG_; }
        // aI now at row h0+5 (add stream); sub stream starts at h0-4.
        const float4* sI = I4 + (size_t)(h0 - 4) * WG_;
        const float4* sJ = J4 + (size_t)(h0 - 4) * WG_;
#pragma unroll 2
        for (int i = 0; i < 16; i++) {
            store(h0 + i);
            if (i < 15) {
                accum(aI, aJ, true);  aI += WG_; aJ += WG_;
                accum(sI, sJ, false); sI += WG_; sJ += WG_;
            }
        }
    } else {
        // Boundary chunks (ch 0 and 11): predicated rows.
#pragma unroll 3
        for (int k = -4; k <= 4; k++) {
            const int hr = h0 + k;
            if (hr >= 0 && hr < H_)
                accum(I4 + (size_t)hr * WG_, J4 + (size_t)hr * WG_, true);
        }
#pragma unroll 2
        for (int i = 0; i < 16; i++) {
            store(h0 + i);
            if (i < 15) {
                const int hp = h0 + i + 5, hm = h0 + i - 4;
                if (hp < H_)  accum(I4 + (size_t)hp * WG_, J4 + (size_t)hp * WG_, true);
                if (hm >= 0)  accum(I4 + (size_t)hm * WG_, J4 + (size_t)hm * WG_, false);
            }
        }
    }
}

// ---------------------------------------------------------------------------
// Pass 3: 9-tap box sum along D with half2 slide arithmetic, immediate-offset
// loads (full unroll), interior/boundary specialization. fp32 cc epilogue,
// double reduction, last-block finalization. 245,760 threads.
// ---------------------------------------------------------------------------
__global__ void __launch_bounds__(256) k_p3(float* __restrict__ out) {
    const int t  = blockIdx.x * blockDim.x + threadIdx.x;
    const int wv = t % WG_;
    const int h  = (t / WG_) % H_;
    const int ch = (t / (WG_ * H_)) % NDC_;
    const int b  = t / (WG_ * H_ * NDC_);
    const int d0 = ch * 10;

    const size_t colbase = (size_t)b * D_ * HW_ + (size_t)h * W_ + (size_t)wv * 4;

    const uint2* base2[5];
#pragma unroll
    for (int c = 0; c < 5; c++)
        base2[c] = (const uint2*)&g_A[(size_t)c * N_ + colbase];

    __half2 S[5][2];
    const __half2 hz = __floats2half2_rn(0.f, 0.f);
#pragma unroll
    for (int c = 0; c < 5; c++) { S[c][0] = hz; S[c][1] = hz; }

    const float inv = 1.0f / 729.0f;
    float lacc = 0.f;

    auto ccl = [&](float s0, float s1, float s2, float s3, float s4) {
        const float cross = fmaf(-s0 * inv, s1, s4);
        const float ivar  = fmaf(-s0 * inv, s0, s2);
        const float jvar  = fmaf(-s1 * inv, s1, s3);
        lacc += __fdividef(cross * cross, fmaf(ivar, jvar, 1e-5f));
    };
    auto ccS = [&]() {
        float2 x0 = __half22float2(S[0][0]), y0 = __half22float2(S[0][1]);
        float2 x1 = __half22float2(S[1][0]), y1 = __half22float2(S[1][1]);
        float2 x2 = __half22float2(S[2][0]), y2 = __half22float2(S[2][1]);
        float2 x3 = __half22float2(S[3][0]), y3 = __half22float2(S[3][1]);
        float2 x4 = __half22float2(S[4][0]), y4 = __half22float2(S[4][1]);
        ccl(x0.x, x1.x, x2.x, x3.x, x4.x);
        ccl(x0.y, x1.y, x2.y, x3.y, x4.y);
        ccl(y0.x, y1.x, y2.x, y3.x, y4.x);
        ccl(y0.y, y1.y, y2.y, y3.y, y4.y);
    };

    if (ch > 0 && ch < NDC_ - 1) {
        // Interior: slices d0-4 .. d0+13 all inside [0, D) -> no checks,
        // full unroll gives immediate-offset LDG off 5 base registers.
#pragma unroll
        for (int k = 0; k < 9; k++) {
#pragma unroll
            for (int c = 0; c < 5; c++) {
                const uint2 v = __ldg(base2[c] + (size_t)(d0 - 4 + k) * DS_);
                S[c][0] = __hadd2(S[c][0], u2h(v.x));
                S[c][1] = __hadd2(S[c][1], u2h(v.y));
            }
        }
        ccS();
#pragma unroll
        for (int i = 1; i < 10; i++) {
#pragma unroll
            for (int c = 0; c < 5; c++) {
                const uint2 a_ = __ldg(base2[c] + (size_t)(d0 + 4 + i) * DS_);
                const uint2 s_ = __ldg(base2[c] + (size_t)(d0 - 5 + i) * DS_);
                S[c][0] = __hadd2(S[c][0], __hsub2(u2h(a_.x), u2h(s_.x)));
                S[c][1] = __hadd2(S[c][1], __hsub2(u2h(a_.y), u2h(s_.y)));
            }
            ccS();
        }
    } else {
        // Boundary chunks (ch 0 and 15): predicated slices.
        for (int k = 0; k < 9; k++) {
            const int d = d0 - 4 + k;
            if (d >= 0 && d < D_) {
#pragma unroll
                for (int c = 0; c < 5; c++) {
                    const uint2 v = __ldg(base2[c] + (size_t)d * DS_);
                    S[c][0] = __hadd2(S[c][0], u2h(v.x));
                    S[c][1] = __hadd2(S[c][1], u2h(v.y));
                }
            }
        }
        ccS();
        for (int i = 1; i < 10; i++) {
            const int da = d0 + 4 + i, ds = d0 - 5 + i;
            const bool pa = (da < D_), ps = (ds >= 0);
            const uint2 uz = make_uint2(0u, 0u);
#pragma unroll
            for (int c = 0; c < 5; c++) {
                const uint2 a_ = pa ? __ldg(base2[c] + (size_t)da * DS_) : uz;
                const uint2 s_ = ps ? __ldg(base2[c] + (size_t)ds * DS_) : uz;
                S[c][0] = __hadd2(S[c][0], __hsub2(u2h(a_.x), u2h(s_.x)));
                S[c][1] = __hadd2(S[c][1], __hsub2(u2h(a_.y), u2h(s_.y)));
            }
            ccS();
        }
    }

    // Block reduction in double, one atomic per block, last-block finalizes.
    double v = (double)lacc;
#pragma unroll
    for (int off = 16; off; off >>= 1)
        v += __shfl_down_sync(0xffffffffu, v, off);

    __shared__ double sm[8];
    const int lane = threadIdx.x & 31;
    const int wid  = threadIdx.x >> 5;
    if (lane == 0) sm[wid] = v;
    __syncthreads();
    if (wid == 0) {
        v = (lane < 8) ? sm[lane] : 0.0;
        v += __shfl_down_sync(0xffffffffu, v, 4);
        v += __shfl_down_sync(0xffffffffu, v, 2);
        v += __shfl_down_sync(0xffffffffu, v, 1);
        if (lane == 0) {
            atomicAdd(&g_acc, v);
            __threadfence();
            const unsigned tk = atomicAdd(&g_tk, 1u);
            if (tk == gridDim.x - 1) {
                __threadfence();
                out[0] = (float)(-g_acc / (double)N_);
            }
        }
    }
}

// ---------------------------------------------------------------------------
extern "C" void kernel_launch(void* const* d_in, const int* in_sizes, int n_in,
                              void* d_out, int out_size) {
    const float* y_pred = (const float*)d_in[0];
    const float* y_true = (const float*)d_in[1];

    // 153,600 threads: (plane, h-chunk of 16, w/4)
    k_p12<<<(B_ * D_ * NHC_ * WG_) / 256, 256>>>(y_true, y_pred);

    // 245,760 threads: (b, d-chunk of 10, h, w/4), fused finalization
    k_p3<<<(B_ * NDC_ * H_ * WG_) / 256, 256>>>((float*)d_out);
}

// round 10
// speedup vs baseline: 1.3646x; 1.3646x over previous
#include <cuda_runtime.h>
#include <cuda_fp16.h>

// Problem geometry (fixed per reference setup_inputs)
#define B_ 2
#define D_ 160
#define H_ 192
#define W_ 160
constexpr size_t N_  = (size_t)B_ * D_ * H_ * W_;   // 9,830,400
constexpr size_t HW_ = (size_t)H_ * W_;
#define WG_ 40   // float4 groups along w
#define NHC_ 24  // h-chunks (8 rows each)
#define NDC_ 16  // d-chunks (10 slices each)
#define DS_  ((int)(HW_ / 4))   // uint2 elements per d-slice (7680)

// Intermediate: 5 channels (I_s, J_s, I2_s, J2_s, IJ_s), W+H convolved, fp16.
__device__ __half g_A[5 * N_];
__device__ double g_acc;
__device__ unsigned g_tk;

// ---------------------------------------------------------------------------
// Helpers
// ---------------------------------------------------------------------------
__device__ __forceinline__ float4 f4z() { return make_float4(0.f, 0.f, 0.f, 0.f); }
__device__ __forceinline__ __half2 u2h(unsigned u) { return *(__half2*)&u; }

__device__ __forceinline__ uint2 f4_to_h4(float4 v) {
    __half2 lo = __floats2half2_rn(v.x, v.y);
    __half2 hi = __floats2half2_rn(v.z, v.w);
    uint2 r;
    r.x = *(const unsigned*)&lo;
    r.y = *(const unsigned*)&hi;
    return r;
}

// 9-tap window sums per lane from a 12-float sequence x[0..11] (x[0] = w-4).
__device__ __forceinline__ float4 win9(const float* x) {
    float s = x[0]+x[1]+x[2]+x[3]+x[4]+x[5]+x[6]+x[7]+x[8];
    float4 r;
    r.x = s;
    s += x[9]  - x[0]; r.y = s;
    s += x[10] - x[1]; r.z = s;
    s += x[11] - x[2]; r.w = s;
    return r;
}

// ---------------------------------------------------------------------------
// Fused pass 1+2: 9-tap box sums along W and H, float4-vectorized, fp16 out.
// Thread = (plane, h-chunk of 8, 4-wide w group). 307,200 threads. Slides
// along h via re-read: S += Wrow(h+5) - Wrow(h-4) (subtract row L1/L2-hit).
// ---------------------------------------------------------------------------
__global__ void __launch_bounds__(256) k_p12(const float* __restrict__ I,
                                             const float* __restrict__ J) {
    const int t     = blockIdx.x * blockDim.x + threadIdx.x;
    const int g     = t % WG_;                 // f4 group 0..39
    const int ch    = (t / WG_) % NHC_;        // h-chunk 0..23
    const int plane = t / (WG_ * NHC_);        // b*D + d
    const int h0    = ch * 8;

    if (t == 0) { g_acc = 0.0; g_tk = 0u; }

    const size_t pbase = (size_t)plane * HW_;
    const float4* __restrict__ I4 = (const float4*)(I + pbase);
    const float4* __restrict__ J4 = (const float4*)(J + pbase);

    float4 S0 = f4z(), S1 = f4z(), S2 = f4z(), S3 = f4z(), S4 = f4z();

    auto accum = [&](int hr, float sg) {
        const int rb = hr * WG_;
        float4 qa0 = (g > 0)       ? __ldg(I4 + rb + g - 1) : f4z();
        float4 qa1 =                 __ldg(I4 + rb + g);
        float4 qa2 = (g < WG_ - 1) ? __ldg(I4 + rb + g + 1) : f4z();
        float4 qb0 = (g > 0)       ? __ldg(J4 + rb + g - 1) : f4z();
        float4 qb1 =                 __ldg(J4 + rb + g);
        float4 qb2 = (g < WG_ - 1) ? __ldg(J4 + rb + g + 1) : f4z();

        float a[12] = {qa0.x,qa0.y,qa0.z,qa0.w, qa1.x,qa1.y,qa1.z,qa1.w, qa2.x,qa2.y,qa2.z,qa2.w};
        float b[12] = {qb0.x,qb0.y,qb0.z,qb0.w, qb1.x,qb1.y,qb1.z,qb1.w, qb2.x,qb2.y,qb2.z,qb2.w};

        float4 w0 = win9(a);
        float4 w1 = win9(b);
        float p[12];
#pragma unroll
        for (int i = 0; i < 12; i++) p[i] = a[i] * a[i];
        float4 w2 = win9(p);
#pragma unroll
        for (int i = 0; i < 12; i++) p[i] = b[i] * b[i];
        float4 w3 = win9(p);
#pragma unroll
        for (int i = 0; i < 12; i++) p[i] = a[i] * b[i];
        float4 w4 = win9(p);

        S0.x += sg*w0.x; S0.y += sg*w0.y; S0.z += sg*w0.z; S0.w += sg*w0.w;
        S1.x += sg*w1.x; S1.y += sg*w1.y; S1.z += sg*w1.z; S1.w += sg*w1.w;
        S2.x += sg*w2.x; S2.y += sg*w2.y; S2.z += sg*w2.z; S2.w += sg*w2.w;
        S3.x += sg*w3.x; S3.y += sg*w3.y; S3.z += sg*w3.z; S3.w += sg*w3.w;
        S4.x += sg*w4.x; S4.y += sg*w4.y; S4.z += sg*w4.z; S4.w += sg*w4.w;
    };

    // Prologue: H-window for output row h0 (rows h0-4 .. h0+4)
#pragma unroll
    for (int k = -4; k <= 4; k++) {
        const int hr = h0 + k;
        if (hr >= 0 && hr < H_) accum(hr, 1.f);
    }

#pragma unroll 2
    for (int i = 0; i < 8; i++) {
        const int h = h0 + i;
        const size_t o = pbase + (size_t)h * W_ + (size_t)g * 4;
        *(uint2*)&g_A[0*N_ + o] = f4_to_h4(S0);
        *(uint2*)&g_A[1*N_ + o] = f4_to_h4(S1);
        *(uint2*)&g_A[2*N_ + o] = f4_to_h4(S2);
        *(uint2*)&g_A[3*N_ + o] = f4_to_h4(S3);
        *(uint2*)&g_A[4*N_ + o] = f4_to_h4(S4);

        if (i < 7) {
            const int hp = h + 5, hm = h - 4;
            if (hp < H_)  accum(hp,  1.f);
            if (hm >= 0)  accum(hm, -1.f);
        }
    }
}

// ---------------------------------------------------------------------------
// Pass 3: 9-tap box sum along D with half2 slide arithmetic, immediate-offset
// loads (full unroll), interior/boundary specialization. fp32 cc epilogue,
// double reduction, last-block finalization. 245,760 threads.
// ---------------------------------------------------------------------------
__global__ void __launch_bounds__(256) k_p3(float* __restrict__ out) {
    const int t  = blockIdx.x * blockDim.x + threadIdx.x;
    const int wv = t % WG_;
    const int h  = (t / WG_) % H_;
    const int ch = (t / (WG_ * H_)) % NDC_;
    const int b  = t / (WG_ * H_ * NDC_);
    const int d0 = ch * 10;

    const size_t colbase = (size_t)b * D_ * HW_ + (size_t)h * W_ + (size_t)wv * 4;

    const uint2* base2[5];
#pragma unroll
    for (int c = 0; c < 5; c++)
        base2[c] = (const uint2*)&g_A[(size_t)c * N_ + colbase];

    __half2 S[5][2];
    const __half2 hz = __floats2half2_rn(0.f, 0.f);
#pragma unroll
    for (int c = 0; c < 5; c++) { S[c][0] = hz; S[c][1] = hz; }

    const float inv = 1.0f / 729.0f;
    float lacc = 0.f;

    auto ccl = [&](float s0, float s1, float s2, float s3, float s4) {
        const float cross = fmaf(-s0 * inv, s1, s4);
        const float ivar  = fmaf(-s0 * inv, s0, s2);
        const float jvar  = fmaf(-s1 * inv, s1, s3);
        lacc += __fdividef(cross * cross, fmaf(ivar, jvar, 1e-5f));
    };
    auto ccS = [&]() {
        float2 x0 = __half22float2(S[0][0]), y0 = __half22float2(S[0][1]);
        float2 x1 = __half22float2(S[1][0]), y1 = __half22float2(S[1][1]);
        float2 x2 = __half22float2(S[2][0]), y2 = __half22float2(S[2][1]);
        float2 x3 = __half22float2(S[3][0]), y3 = __half22float2(S[3][1]);
        float2 x4 = __half22float2(S[4][0]), y4 = __half22float2(S[4][1]);
        ccl(x0.x, x1.x, x2.x, x3.x, x4.x);
        ccl(x0.y, x1.y, x2.y, x3.y, x4.y);
        ccl(y0.x, y1.x, y2.x, y3.x, y4.x);
        ccl(y0.y, y1.y, y2.y, y3.y, y4.y);
    };

    if (ch > 0 && ch < NDC_ - 1) {
        // Interior: slices d0-4 .. d0+13 all inside [0, D) -> no checks,
        // full unroll gives immediate-offset LDG off 5 base registers.
#pragma unroll
        for (int k = 0; k < 9; k++) {
#pragma unroll
            for (int c = 0; c < 5; c++) {
                const uint2 v = __ldg(base2[c] + (size_t)(d0 - 4 + k) * DS_);
                S[c][0] = __hadd2(S[c][0], u2h(v.x));
                S[c][1] = __hadd2(S[c][1], u2h(v.y));
            }
        }
        ccS();
#pragma unroll
        for (int i = 1; i < 10; i++) {
#pragma unroll
            for (int c = 0; c < 5; c++) {
                const uint2 a_ = __ldg(base2[c] + (size_t)(d0 + 4 + i) * DS_);
                const uint2 s_ = __ldg(base2[c] + (size_t)(d0 - 5 + i) * DS_);
                S[c][0] = __hadd2(S[c][0], __hsub2(u2h(a_.x), u2h(s_.x)));
                S[c][1] = __hadd2(S[c][1], __hsub2(u2h(a_.y), u2h(s_.y)));
            }
            ccS();
        }
    } else {
        // Boundary chunks (ch 0 and 15): predicated slices.
        for (int k = 0; k < 9; k++) {
            const int d = d0 - 4 + k;
            if (d >= 0 && d < D_) {
#pragma unroll
                for (int c = 0; c < 5; c++) {
                    const uint2 v = __ldg(base2[c] + (size_t)d * DS_);
                    S[c][0] = __hadd2(S[c][0], u2h(v.x));
                    S[c][1] = __hadd2(S[c][1], u2h(v.y));
                }
            }
        }
        ccS();
        for (int i = 1; i < 10; i++) {
            const int da = d0 + 4 + i, ds = d0 - 5 + i;
            const bool pa = (da < D_), ps = (ds >= 0);
            const uint2 uz = make_uint2(0u, 0u);
#pragma unroll
            for (int c = 0; c < 5; c++) {
                const uint2 a_ = pa ? __ldg(base2[c] + (size_t)da * DS_) : uz;
                const uint2 s_ = ps ? __ldg(base2[c] + (size_t)ds * DS_) : uz;
                S[c][0] = __hadd2(S[c][0], __hsub2(u2h(a_.x), u2h(s_.x)));
                S[c][1] = __hadd2(S[c][1], __hsub2(u2h(a_.y), u2h(s_.y)));
            }
            ccS();
        }
    }

    // Block reduction in double, one atomic per block, last-block finalizes.
    double v = (double)lacc;
#pragma unroll
    for (int off = 16; off; off >>= 1)
        v += __shfl_down_sync(0xffffffffu, v, off);

    __shared__ double sm[8];
    const int lane = threadIdx.x & 31;
    const int wid  = threadIdx.x >> 5;
    if (lane == 0) sm[wid] = v;
    __syncthreads();
    if (wid == 0) {
        v = (lane < 8) ? sm[lane] : 0.0;
        v += __shfl_down_sync(0xffffffffu, v, 4);
        v += __shfl_down_sync(0xffffffffu, v, 2);
        v += __shfl_down_sync(0xffffffffu, v, 1);
        if (lane == 0) {
            atomicAdd(&g_acc, v);
            __threadfence();
            const unsigned tk = atomicAdd(&g_tk, 1u);
            if (tk == gridDim.x - 1) {
                __threadfence();
                out[0] = (float)(-g_acc / (double)N_);
            }
        }
    }
}

// ---------------------------------------------------------------------------
extern "C" void kernel_launch(void* const* d_in, const int* in_sizes, int n_in,
                              void* d_out, int out_size) {
    const float* y_pred = (const float*)d_in[0];
    const float* y_true = (const float*)d_in[1];

    // 307,200 threads: (plane, h-chunk of 8, w/4)
    k_p12<<<(B_ * D_ * NHC_ * WG_) / 256, 256>>>(y_true, y_pred);

    // 245,760 threads: (b, d-chunk of 10, h, w/4), fused finalization
    k_p3<<<(B_ * NDC_ * H_ * WG_) / 256, 256>>>((float*)d_out);
}